// round 14
// baseline (speedup 1.0000x reference)
#include <cuda_runtime.h>
#include <cuda_bf16.h>
#include <math.h>
#include <stdint.h>

#define NN 4096
#define FF 128
#define OC 80            // Y cols (73 used)
#define KCH 4
#define GBM 128
#define GBK 32

// gemm dynamic smem: A 4 stages x (128 rows x 160B fp32-padded), B 4 x (160 x 64B)
#define GA_STRIDE 160
#define GA_STAGE  (GBM * GA_STRIDE)          // 20480
#define GB_STAGE  (160 * 64)                 // 10240
#define G_AOFF    0
#define G_BOFF    (4 * GA_STAGE)             // 81920
#define GEMM_SMEM (4 * GA_STAGE + 4 * GB_STAGE)  // 122880

// prep dynamic smem
#define P_AOFF 0                              // Hc: 8 chunks x 64 rows x 64B = 32768
#define P_BOFF 32768                          // Wc: 8 chunks x 64 rows x 64B = 32768
#define P_COFF 65536                          // sC: 72 x 64 fp32 = 18432
#define P_ALOFF 83968
#define P_AROFF 84224
#define PREP_SMEM 84480

__device__ __nv_bfloat16 g_Mt[160 * NN];     // B op: row 2c = hi of col c, 2c+1 = lo
__device__ float g_EL[8 * NN];
__device__ float g_Ypart[KCH][NN * OC];

__device__ __forceinline__ uint32_t smem_u32(const void* p) {
    uint32_t a;
    asm("{ .reg .u64 t; cvta.to.shared.u64 t, %1; cvt.u32.u64 %0, t; }" : "=r"(a) : "l"(p));
    return a;
}
__device__ __forceinline__ void ldm4(uint32_t* r, uint32_t addr) {
    asm volatile("ldmatrix.sync.aligned.m8n8.x4.shared.b16 {%0,%1,%2,%3}, [%4];"
                 : "=r"(r[0]), "=r"(r[1]), "=r"(r[2]), "=r"(r[3]) : "r"(addr));
}
__device__ __forceinline__ void mma16816(float* c, const uint32_t* a, const uint32_t* b) {
    asm volatile("mma.sync.aligned.m16n8k16.row.col.f32.bf16.bf16.f32 "
                 "{%0,%1,%2,%3}, {%4,%5,%6,%7}, {%8,%9}, {%0,%1,%2,%3};"
                 : "+f"(c[0]), "+f"(c[1]), "+f"(c[2]), "+f"(c[3])
                 : "r"(a[0]), "r"(a[1]), "r"(a[2]), "r"(a[3]), "r"(b[0]), "r"(b[1]));
}
__device__ __forceinline__ void cpa16(uint32_t dst, const void* src) {
    asm volatile("cp.async.cg.shared.global [%0], [%1], 16;" :: "r"(dst), "l"(src));
}
__device__ __forceinline__ uint32_t packbf2(float a, float b) {
    __nv_bfloat162 p = __floats2bfloat162_rn(a, b);
    return *(uint32_t*)&p;
}

// ---------------------------------------------------------------------------
// Kernel 1 (tensor prep): acc[j,hu] = H[j,:] @ Wcat[:,hu] via split-bf16 HMMA
// (Hhi*Whi + Hhi*Wlo + Hlo*Whi). 64 blocks x 64 nodes. Then e_l/e_r/exp and
// emit g_Mt (hi/lo interleaved, transposed) + g_EL.
// ---------------------------------------------------------------------------
__global__ void __launch_bounds__(256) prep_kernel(const float* __restrict__ H,
                                                   const float* __restrict__ W,
                                                   const float* __restrict__ al,
                                                   const float* __restrict__ ar) {
    extern __shared__ __align__(1024) char dsm[];
    uint32_t sbase = smem_u32(dsm);
    int tid = threadIdx.x;
    int lane = tid & 31, wid = tid >> 5;
    int j0 = blockIdx.x * 64;

    if (tid < 64) {
        *(float*)(dsm + P_ALOFF + tid * 4) = al[tid];
        *(float*)(dsm + P_AROFF + tid * 4) = ar[tid];
    }

    // stage Wc: Whi -> chunks 0..3, Wlo -> chunks 4..7 of B region
#pragma unroll 4
    for (int it = 0; it < 32; it++) {
        int lin = tid + it * 256;                 // h*1024 + f*8 + u
        int h = lin >> 10, f = (lin >> 3) & 127, u = lin & 7;
        int hu = h * 8 + u;
        float w = W[lin];
        __nv_bfloat16 whi = __float2bfloat16_rn(w);
        __nv_bfloat16 wlo = __float2bfloat16_rn(w - __bfloat162float(whi));
        uint32_t off = hu * 64 + (((f & 31) * 2) ^ (((hu >> 1) & 3) << 4));
        *(__nv_bfloat16*)(dsm + P_BOFF + (f >> 5) * 4096 + off) = whi;
        *(__nv_bfloat16*)(dsm + P_BOFF + (4 + (f >> 5)) * 4096 + off) = wlo;
    }
    // stage Hc: Hhi -> chunks 0..3, Hlo -> chunks 4..7 of A region
#pragma unroll
    for (int it = 0; it < 8; it++) {
        int lin = tid + it * 256;                 // 64 rows x 32 f-quads
        int m = lin >> 5, kq = lin & 31;
        float4 v = *(const float4*)(H + (size_t)(j0 + m) * FF + kq * 4);
        uint32_t hi0 = packbf2(v.x, v.y), hi1 = packbf2(v.z, v.w);
        float4 r;
        r.x = v.x - __bfloat162float(__float2bfloat16_rn(v.x));
        r.y = v.y - __bfloat162float(__float2bfloat16_rn(v.y));
        r.z = v.z - __bfloat162float(__float2bfloat16_rn(v.z));
        r.w = v.w - __bfloat162float(__float2bfloat16_rn(v.w));
        uint32_t lo0 = packbf2(r.x, r.y), lo1 = packbf2(r.z, r.w);
        uint32_t off = m * 64 + (((kq & 7) * 8) ^ (((m >> 1) & 3) << 4));
        uint2 whi; whi.x = hi0; whi.y = hi1;
        uint2 wlo; wlo.x = lo0; wlo.y = lo1;
        *(uint2*)(dsm + P_AOFF + (kq >> 3) * 4096 + off) = whi;
        *(uint2*)(dsm + P_AOFF + (4 + (kq >> 3)) * 4096 + off) = wlo;
    }
    __syncthreads();

    int rg = wid & 3, cg = wid >> 2;              // 4 row-groups x 2 col-groups
    // ldmatrix addresses
    int arow = rg * 16 + (lane & 15);
    uint32_t abase = arow * 64;
    uint32_t akx = ((arow >> 1) & 3) << 4;
    uint32_t khA = (lane >> 4) << 4;
    uint32_t bbase[2], bkx[2];
#pragma unroll
    for (int g = 0; g < 2; g++) {
        int n = cg * 32 + g * 16 + (lane & 7) + ((lane >> 4) << 3);
        bbase[g] = n * 64;
        bkx[g] = ((n >> 1) & 3) << 4;
    }
    uint32_t khB = ((lane >> 3) & 1) << 4;

    float acc[4][4];
#pragma unroll
    for (int t = 0; t < 4; t++)
#pragma unroll
        for (int q = 0; q < 4; q++) acc[t][q] = 0.f;

#pragma unroll
    for (int s = 0; s < 24; s++) {
        int cA = (s < 8) ? (s >> 1) : (s < 16 ? ((s - 8) >> 1) : 4 + ((s - 16) >> 1));
        int cB = (s < 16) ? (s >> 1) : ((s - 16) >> 1);
        uint32_t kk = (s & 1) << 5;
        uint32_t a[4];
        ldm4(a, sbase + P_AOFF + cA * 4096 + abase + ((kk | khA) ^ akx));
        uint32_t bb[4][2];
#pragma unroll
        for (int g = 0; g < 2; g++) {
            uint32_t tr[4];
            ldm4(tr, sbase + P_BOFF + cB * 4096 + bbase[g] + ((kk | khB) ^ bkx[g]));
            bb[2 * g][0] = tr[0]; bb[2 * g][1] = tr[1];
            bb[2 * g + 1][0] = tr[2]; bb[2 * g + 1][1] = tr[3];
        }
#pragma unroll
        for (int t = 0; t < 4; t++) mma16816(acc[t], a, bb[t]);
    }

    // epilogue: per head (n8 tile), reduce over u (4 lanes x 2 cols) for e_l/e_r
    int r1 = rg * 16 + (lane >> 2);
    int r2 = r1 + 8;
    int u0 = 2 * (lane & 3);
#pragma unroll
    for (int t = 0; t < 4; t++) {
        int h = cg * 4 + t;
        float al0 = *(float*)(dsm + P_ALOFF + (h * 8 + u0) * 4);
        float al1 = *(float*)(dsm + P_ALOFF + (h * 8 + u0 + 1) * 4);
        float ar0 = *(float*)(dsm + P_AROFF + (h * 8 + u0) * 4);
        float ar1 = *(float*)(dsm + P_AROFF + (h * 8 + u0 + 1) * 4);
        float pl1 = acc[t][0] * al0 + acc[t][1] * al1;
        float pr1 = acc[t][0] * ar0 + acc[t][1] * ar1;
        float pl2 = acc[t][2] * al0 + acc[t][3] * al1;
        float pr2 = acc[t][2] * ar0 + acc[t][3] * ar1;
#pragma unroll
        for (int m = 1; m <= 2; m <<= 1) {
            pl1 += __shfl_xor_sync(0xffffffffu, pl1, m);
            pr1 += __shfl_xor_sync(0xffffffffu, pr1, m);
            pl2 += __shfl_xor_sync(0xffffffffu, pl2, m);
            pr2 += __shfl_xor_sync(0xffffffffu, pr2, m);
        }
        float eer1 = expf(pr1), eer2 = expf(pr2);
        float* sC = (float*)(dsm + P_COFF);
        sC[(h * 9 + u0) * 64 + r1]     = eer1 * acc[t][0];
        sC[(h * 9 + u0 + 1) * 64 + r1] = eer1 * acc[t][1];
        sC[(h * 9 + u0) * 64 + r2]     = eer2 * acc[t][2];
        sC[(h * 9 + u0 + 1) * 64 + r2] = eer2 * acc[t][3];
        if ((lane & 3) == 0) {
            sC[(h * 9 + 8) * 64 + r1] = eer1;
            sC[(h * 9 + 8) * 64 + r2] = eer2;
            g_EL[h * NN + j0 + r1] = pl1;
            g_EL[h * NN + j0 + r2] = pl2;
        }
    }
    __syncthreads();

    const float* sC = (const float*)(dsm + P_COFF);
    for (int idx = tid; idx < 146 * 64; idx += 256) {
        int r = idx >> 6, jl = idx & 63;
        int c = r >> 1;
        float v = (c == 72) ? 1.0f : sC[c * 64 + jl];
        __nv_bfloat16 hi = __float2bfloat16_rn(v);
        __nv_bfloat16 o = (r & 1) ? __float2bfloat16_rn(v - __bfloat162float(hi)) : hi;
        g_Mt[(size_t)r * NN + j0 + jl] = o;
    }
}

// ---------------------------------------------------------------------------
// Kernel 2: HMMA GEMM, cp.async 4-stage pipeline. A staged as fp32 (pad-160B
// rows), converted to bf16 fragments at consume; B bf16 via cp.async direct.
// ---------------------------------------------------------------------------
__global__ void __launch_bounds__(256) gemm_kernel(const float* __restrict__ A) {
    extern __shared__ __align__(1024) char dsm[];
    uint32_t sbase = smem_u32(dsm);

    int tid = threadIdx.x;
    int lane = tid & 31, wid = tid >> 5;
    int rg = wid & 3, cg = wid >> 2;              // 4 x 2 warps

    const size_t arow0 = (size_t)(blockIdx.x * GBM) * NN + (size_t)blockIdx.y * (NN / KCH);
    const __nv_bfloat16* Bp = g_Mt + (size_t)blockIdx.y * (NN / KCH);

    // B ldmatrix addresses (SW64, proven)
    uint32_t bbase[5], bkx[5];
#pragma unroll
    for (int g = 0; g < 5; g++) {
        int n = cg * 80 + g * 16 + (lane & 7) + ((lane >> 4) << 3);
        bbase[g] = n * 64;
        bkx[g] = ((n >> 1) & 3) << 4;
    }
    uint32_t khB = ((lane >> 3) & 1) << 4;

    // A consume base rows
    int arow1 = rg * 32 + (lane >> 2);            // +0/+8/+16/+24 variants
    int akb = (lane & 3) * 2;                     // k pair base

    float acc[2][10][4];
#pragma unroll
    for (int mt = 0; mt < 2; mt++)
#pragma unroll
        for (int t = 0; t < 10; t++)
#pragma unroll
            for (int q = 0; q < 4; q++) acc[mt][t][q] = 0.f;

#define ISSUE(chunk, stage)                                                     \
    {                                                                           \
        int kc = (chunk) * GBK;                                                 \
        uint32_t adst = sbase + G_AOFF + (stage) * GA_STAGE;                    \
        _Pragma("unroll") for (int t = 0; t < 4; t++) {                         \
            int lin = tid + t * 256;                                            \
            int m = lin >> 3, kq = lin & 7;                                     \
            cpa16(adst + m * GA_STRIDE + kq * 16,                               \
                  A + arow0 + (size_t)m * NN + kc + kq * 4);                    \
        }                                                                       \
        uint32_t bdst = sbase + G_BOFF + (stage) * GB_STAGE;                    \
        _Pragma("unroll") for (int t = 0; t < 3; t++) {                         \
            int lin = tid + t * 256;                                            \
            if (lin < 640) {                                                    \
                int m = lin >> 2, kq = lin & 3;                                 \
                cpa16(bdst + m * 64 + ((kq * 16) ^ (((m >> 1) & 3) << 4)),      \
                      Bp + (size_t)m * NN + kc + kq * 8);                       \
            }                                                                   \
        }                                                                       \
        asm volatile("cp.async.commit_group;" ::: "memory");                    \
    }

    ISSUE(0, 0); ISSUE(1, 1); ISSUE(2, 2);

    for (int i = 0; i < 32; i++) {
        asm volatile("cp.async.wait_group 2;" ::: "memory");
        __syncthreads();
        if (i + 3 < 32) { ISSUE(i + 3, (i + 3) & 3); }
        else { asm volatile("cp.async.commit_group;" ::: "memory"); }

        const char* aBuf = dsm + G_AOFF + (i & 3) * GA_STAGE;
        uint32_t bBuf = sbase + G_BOFF + (i & 3) * GB_STAGE;
#pragma unroll
        for (int ks = 0; ks < 2; ks++) {
            uint32_t kk = ks << 5;
            int kb = ks * 16 + akb;
            uint32_t a[2][4];
#pragma unroll
            for (int mt = 0; mt < 2; mt++) {
                int r = arow1 + mt * 16;
                float2 f0 = *(const float2*)(aBuf + r * GA_STRIDE + kb * 4);
                float2 f1 = *(const float2*)(aBuf + (r + 8) * GA_STRIDE + kb * 4);
                float2 f2 = *(const float2*)(aBuf + r * GA_STRIDE + (kb + 8) * 4);
                float2 f3 = *(const float2*)(aBuf + (r + 8) * GA_STRIDE + (kb + 8) * 4);
                a[mt][0] = packbf2(f0.x, f0.y);
                a[mt][1] = packbf2(f1.x, f1.y);
                a[mt][2] = packbf2(f2.x, f2.y);
                a[mt][3] = packbf2(f3.x, f3.y);
            }
            uint32_t bb[10][2];
#pragma unroll
            for (int g = 0; g < 5; g++) {
                uint32_t tr[4];
                ldm4(tr, bBuf + bbase[g] + ((kk | khB) ^ bkx[g]));
                bb[2 * g][0] = tr[0]; bb[2 * g][1] = tr[1];
                bb[2 * g + 1][0] = tr[2]; bb[2 * g + 1][1] = tr[3];
            }
#pragma unroll
            for (int mt = 0; mt < 2; mt++)
#pragma unroll
                for (int t = 0; t < 10; t++)
                    mma16816(acc[mt][t], a[mt], bb[t]);
        }
    }

    // Epilogue: pair-sum hi/lo D columns
    float* Yp = g_Ypart[blockIdx.y];
    int rbase = blockIdx.x * GBM + rg * 32 + (lane >> 2);
    int cbase = cg * 40 + (lane & 3);
#pragma unroll
    for (int mt = 0; mt < 2; mt++)
#pragma unroll
        for (int t = 0; t < 10; t++) {
            int r = rbase + mt * 16;
            int c = cbase + t * 4;
            Yp[(size_t)r * OC + c]       = acc[mt][t][0] + acc[mt][t][1];
            Yp[(size_t)(r + 8) * OC + c] = acc[mt][t][2] + acc[mt][t][3];
        }
}

// ---------------------------------------------------------------------------
// Kernel 3: combine partials, denom, elu, write [N, 64]
// ---------------------------------------------------------------------------
__global__ void __launch_bounds__(256) finalize_kernel(float* __restrict__ out) {
    int tid = threadIdx.x;
    int t = tid & 63;
    int i = blockIdx.x * 4 + (tid >> 6);
    int h = t >> 3, u = t & 7;

    float y = 0.f, s = 0.f, deg = 0.f;
#pragma unroll
    for (int p = 0; p < KCH; p++) {
        const float* Yp = g_Ypart[p] + (size_t)i * OC;
        y   += Yp[h * 9 + u];
        s   += Yp[h * 9 + 8];
        deg += Yp[72];
    }
    float eel = expf(g_EL[h * NN + i]);
    float denom = ((float)NN - deg) + eel * s;
    float v = eel * y / denom;
    out[i * 64 + t] = (v > 0.f) ? v : expm1f(v);
}

// ---------------------------------------------------------------------------
extern "C" void kernel_launch(void* const* d_in, const int* in_sizes, int n_in,
                              void* d_out, int out_size) {
    const float* A  = (const float*)d_in[0];
    const float* H  = (const float*)d_in[1];
    const float* W  = (const float*)d_in[2];
    const float* al = (const float*)d_in[3];
    const float* ar = (const float*)d_in[4];
    float* out = (float*)d_out;

    cudaFuncSetAttribute(prep_kernel, cudaFuncAttributeMaxDynamicSharedMemorySize,
                         PREP_SMEM);
    cudaFuncSetAttribute(gemm_kernel, cudaFuncAttributeMaxDynamicSharedMemorySize,
                         GEMM_SMEM);

    prep_kernel<<<64, 256, PREP_SMEM>>>(H, W, al, ar);
    dim3 grid(NN / GBM, KCH);
    gemm_kernel<<<grid, 256, GEMM_SMEM>>>(A);
    finalize_kernel<<<1024, 256>>>(out);
}

// round 17
// speedup vs baseline: 1.3629x; 1.3629x over previous
#include <cuda_runtime.h>
#include <cuda_bf16.h>
#include <math.h>
#include <stdint.h>

#define NN 4096
#define FF 128
#define OC 80            // Y cols (73 used: 8 heads x (8 V + exp_er) + deg)
#define KCH 4            // K-split of GEMM
#define GBM 128          // GEMM row tile per CTA
#define GBK 32           // GEMM k chunk (32 bf16 = 64B rows, SW64 swizzle)

// Scratch (__device__ globals; zero-initialized, rows 146..159 of g_Mt stay 0)
__device__ __nv_bfloat16 g_Mt[160 * NN];     // B op: row 2c = hi of col c, 2c+1 = lo
__device__ float g_EL[8 * NN];
__device__ float g_Ypart[KCH][NN * OC];
__device__ float g_Wt[64 * FF];              // W transposed: [hu][f]

__device__ __forceinline__ uint32_t smem_u32(const void* p) {
    uint32_t a;
    asm("{ .reg .u64 t; cvta.to.shared.u64 t, %1; cvt.u32.u64 %0, t; }" : "=r"(a) : "l"(p));
    return a;
}
__device__ __forceinline__ void ldm4(uint32_t* r, uint32_t addr) {
    asm volatile("ldmatrix.sync.aligned.m8n8.x4.shared.b16 {%0,%1,%2,%3}, [%4];"
                 : "=r"(r[0]), "=r"(r[1]), "=r"(r[2]), "=r"(r[3]) : "r"(addr));
}
__device__ __forceinline__ void mma16816(float* c, const uint32_t* a, const uint32_t* b) {
    asm volatile("mma.sync.aligned.m16n8k16.row.col.f32.bf16.bf16.f32 "
                 "{%0,%1,%2,%3}, {%4,%5,%6,%7}, {%8,%9}, {%0,%1,%2,%3};"
                 : "+f"(c[0]), "+f"(c[1]), "+f"(c[2]), "+f"(c[3])
                 : "r"(a[0]), "r"(a[1]), "r"(a[2]), "r"(a[3]), "r"(b[0]), "r"(b[1]));
}
__device__ __forceinline__ void cpa16(uint32_t dst, const void* src) {
    asm volatile("cp.async.cg.shared.global [%0], [%1], 16;" :: "r"(dst), "l"(src));
}

// ---------------------------------------------------------------------------
// Kernel 0: one-time W transpose [h][f][u] -> g_Wt[hu][f]
// ---------------------------------------------------------------------------
__global__ void wtrans_kernel(const float* __restrict__ W) {
    int lin = (blockIdx.x * 256 + threadIdx.x) * 4;   // u varies within float4
    float4 v = *(const float4*)(W + lin);
    int h = lin >> 10, f = (lin >> 3) & 127, u = lin & 7;
    float* dst = g_Wt + (h * 8 + u) * FF + f;
    dst[0 * FF] = v.x;
    dst[1 * FF] = v.y;
    dst[2 * FF] = v.z;
    dst[3 * FF] = v.w;
}

// ---------------------------------------------------------------------------
// Kernel 1: per node j compute V/e_l/e_r; emit transposed split-bf16 B matrix.
// 256 blocks x 256 threads, 16 nodes/block. Thread (hu, jj) accumulates 4 j's.
// Staging via cp.async straight into padded smem (no scatter, no reg round-trip).
// ---------------------------------------------------------------------------
__global__ void __launch_bounds__(256) prep_kernel(const float* __restrict__ H,
                                                   const float* __restrict__ al,
                                                   const float* __restrict__ ar) {
    __shared__ __align__(16) float sW[64 * 132];  // [hu][f], pad 132 (528B rows)
    __shared__ __align__(16) float sH[16 * FF];   // [j][f]
    __shared__ float sC[72][16];

    int tid = threadIdx.x;
    int j0 = blockIdx.x * 16;
    uint32_t swb = smem_u32(sW);
    uint32_t shb = smem_u32(sH);

    // stage W (2048 x 16B) and H (512 x 16B) via cp.async
#pragma unroll
    for (int it = 0; it < 8; it++) {
        int lin = tid + it * 256;
        int r = lin >> 5, c = lin & 31;
        cpa16(swb + r * 528 + c * 16, g_Wt + r * FF + c * 4);
    }
#pragma unroll
    for (int it = 0; it < 2; it++) {
        int lin = tid + it * 256;
        cpa16(shb + lin * 16, H + (size_t)j0 * FF + lin * 4);
    }
    asm volatile("cp.async.commit_group;" ::: "memory");

    int hu = tid & 63, jj = tid >> 6;
    int h = hu >> 3, u = hu & 7;
    float alv = al[hu], arv = ar[hu];

    asm volatile("cp.async.wait_group 0;" ::: "memory");
    __syncthreads();

    float acc[4] = {0.f, 0.f, 0.f, 0.f};
    const float* wp = sW + hu * 132;
    const float* hp = sH + jj * 4 * FF;
#pragma unroll 8
    for (int f = 0; f < FF; f += 4) {
        float4 wv = *(const float4*)(wp + f);
#pragma unroll
        for (int jg = 0; jg < 4; jg++) {
            float4 hv = *(const float4*)(hp + jg * FF + f);
            acc[jg] += hv.x * wv.x + hv.y * wv.y + hv.z * wv.z + hv.w * wv.w;
        }
    }

#pragma unroll
    for (int jg = 0; jg < 4; jg++) {
        int jl = jj * 4 + jg;
        float el = acc[jg] * alv, er = acc[jg] * arv;
#pragma unroll
        for (int m = 4; m; m >>= 1) {
            el += __shfl_xor_sync(0xffffffffu, el, m);
            er += __shfl_xor_sync(0xffffffffu, er, m);
        }
        float eer = expf(er);
        sC[h * 9 + u][jl] = eer * acc[jg];        // V[h,j,u]
        if (u == 0) {
            sC[h * 9 + 8][jl] = eer;              // exp(e_r)
            g_EL[h * NN + j0 + jl] = el;
        }
    }
    __syncthreads();

    // 146 bf16 rows (hi/lo interleaved), along j
    for (int idx = tid; idx < 146 * 16; idx += 256) {
        int r = idx >> 4, jl = idx & 15;
        int c = r >> 1;
        float v = (c == 72) ? 1.0f : sC[c][jl];
        __nv_bfloat16 hi = __float2bfloat16_rn(v);
        __nv_bfloat16 o = (r & 1) ? __float2bfloat16_rn(v - __bfloat162float(hi)) : hi;
        g_Mt[(size_t)r * NN + j0 + jl] = o;
    }
}

// ---------------------------------------------------------------------------
// Kernel 2: HMMA bf16 GEMM  Ypart[ks] = A_rows x Mt^T  (128 x 160 x 1024/CTA)
// grid (32, 4) = 128 CTAs = one wave. Warp grid 4x2: 32 rows x 80 cols/warp.
// (round-10 proven version, unchanged)
// ---------------------------------------------------------------------------
__global__ void __launch_bounds__(256) gemm_kernel(const float* __restrict__ A) {
    __shared__ __align__(128) __nv_bfloat16 sA[2][GBM * GBK];   // 2 x 8 KB
    __shared__ __align__(128) __nv_bfloat16 sB[2][160 * GBK];   // 2 x 10 KB

    int tid = threadIdx.x;
    int lane = tid & 31, wid = tid >> 5;
    int rg = wid & 3, cg = wid >> 2;              // warp grid 4 x 2

    const size_t arow0 = (size_t)(blockIdx.x * GBM) * NN + (size_t)blockIdx.y * (NN / KCH);
    const __nv_bfloat16* Bp = g_Mt + (size_t)blockIdx.y * (NN / KCH);

    uint32_t saA = smem_u32(sA);
    uint32_t saB = smem_u32(sB);

    // ldmatrix source addresses (SW64: bits[5:4] ^= row bits[2:1])
    uint32_t abase[2], akx[2];
#pragma unroll
    for (int mt = 0; mt < 2; mt++) {
        int row = rg * 32 + mt * 16 + (lane & 15);
        abase[mt] = row * 64;
        akx[mt] = ((row >> 1) & 3) << 4;
    }
    uint32_t khA = (lane >> 4) << 4;

    uint32_t bbase[5], bkx[5];
#pragma unroll
    for (int g = 0; g < 5; g++) {
        int n = cg * 80 + g * 16 + (lane & 7) + ((lane >> 4) << 3);
        bbase[g] = n * 64;
        bkx[g] = ((n >> 1) & 3) << 4;
    }
    uint32_t khB = ((lane >> 3) & 1) << 4;

    // staging store offsets
    uint32_t stA[4], stB[5];
#pragma unroll
    for (int t = 0; t < 4; t++) {
        int lin = tid + t * 256;
        int m = lin >> 3, kq = lin & 7;
        stA[t] = m * 64 + ((kq * 8) ^ (((m >> 1) & 3) << 4));
    }
#pragma unroll
    for (int t = 0; t < 5; t++) {
        int lin = tid + t * 256;
        int m = lin >> 3, kq = lin & 7;
        stB[t] = m * 64 + ((kq * 8) ^ (((m >> 1) & 3) << 4));
    }

    float acc[2][10][4];
#pragma unroll
    for (int mt = 0; mt < 2; mt++)
#pragma unroll
        for (int t = 0; t < 10; t++)
#pragma unroll
            for (int q = 0; q < 4; q++) acc[mt][t][q] = 0.f;

    float4 pa[4];
    uint2 pb[5];

#define LOAD_CHUNK(i)                                                          \
    {                                                                          \
        int kc = (i) * GBK;                                                    \
        _Pragma("unroll") for (int t = 0; t < 4; t++) {                        \
            int lin = tid + t * 256;                                           \
            int m = lin >> 3, kq = lin & 7;                                    \
            pa[t] = *(const float4*)(A + arow0 + (size_t)m * NN + kc + kq * 4);\
        }                                                                      \
        _Pragma("unroll") for (int t = 0; t < 5; t++) {                        \
            int lin = tid + t * 256;                                           \
            int m = lin >> 3, kq = lin & 7;                                    \
            pb[t] = *(const uint2*)(Bp + (size_t)m * NN + kc + kq * 4);        \
        }                                                                      \
    }

#define STORE_CHUNK(b)                                                         \
    {                                                                          \
        _Pragma("unroll") for (int t = 0; t < 4; t++) {                        \
            __nv_bfloat162 p0 = __floats2bfloat162_rn(pa[t].x, pa[t].y);       \
            __nv_bfloat162 p1 = __floats2bfloat162_rn(pa[t].z, pa[t].w);       \
            uint2 w;                                                           \
            w.x = *(uint32_t*)&p0;                                             \
            w.y = *(uint32_t*)&p1;                                             \
            *(uint2*)((char*)sA[b] + stA[t]) = w;                              \
        }                                                                      \
        _Pragma("unroll") for (int t = 0; t < 5; t++)                          \
            *(uint2*)((char*)sB[b] + stB[t]) = pb[t];                          \
    }

    LOAD_CHUNK(0);
    STORE_CHUNK(0);
    __syncthreads();

    for (int i = 0; i < 32; i++) {
        int b = i & 1;
        if (i < 31) LOAD_CHUNK(i + 1);

        uint32_t bufA = saA + b * (GBM * GBK * 2);
        uint32_t bufB = saB + b * (160 * GBK * 2);
#pragma unroll
        for (int ks = 0; ks < 2; ks++) {
            uint32_t kk = ks << 5;
            uint32_t a[2][4];
            ldm4(a[0], bufA + abase[0] + ((kk | khA) ^ akx[0]));
            ldm4(a[1], bufA + abase[1] + ((kk | khA) ^ akx[1]));
            uint32_t bb[10][2];
#pragma unroll
            for (int g = 0; g < 5; g++) {
                uint32_t tr[4];
                ldm4(tr, bufB + bbase[g] + ((kk | khB) ^ bkx[g]));
                bb[2 * g][0] = tr[0]; bb[2 * g][1] = tr[1];
                bb[2 * g + 1][0] = tr[2]; bb[2 * g + 1][1] = tr[3];
            }
#pragma unroll
            for (int mt = 0; mt < 2; mt++)
#pragma unroll
                for (int t = 0; t < 10; t++)
                    mma16816(acc[mt][t], a[mt], bb[t]);
        }

        if (i < 31) {
            __syncthreads();
            STORE_CHUNK(1 - b);
            __syncthreads();
        }
    }

    // Epilogue: pair-sum hi/lo D columns
    float* Yp = g_Ypart[blockIdx.y];
    int rbase = blockIdx.x * GBM + rg * 32 + (lane >> 2);
    int cbase = cg * 40 + (lane & 3);
#pragma unroll
    for (int mt = 0; mt < 2; mt++)
#pragma unroll
        for (int t = 0; t < 10; t++) {
            int r = rbase + mt * 16;
            int c = cbase + t * 4;
            Yp[(size_t)r * OC + c]       = acc[mt][t][0] + acc[mt][t][1];
            Yp[(size_t)(r + 8) * OC + c] = acc[mt][t][2] + acc[mt][t][3];
        }
}

// ---------------------------------------------------------------------------
// Kernel 3: combine K-split partials, denom, elu, write [N, 64]
// ---------------------------------------------------------------------------
__global__ void __launch_bounds__(256) finalize_kernel(float* __restrict__ out) {
    int tid = threadIdx.x;
    int t = tid & 63;
    int i = blockIdx.x * 4 + (tid >> 6);
    int h = t >> 3, u = t & 7;

    float y = 0.f, s = 0.f, deg = 0.f;
#pragma unroll
    for (int p = 0; p < KCH; p++) {
        const float* Yp = g_Ypart[p] + (size_t)i * OC;
        y   += Yp[h * 9 + u];
        s   += Yp[h * 9 + 8];
        deg += Yp[72];
    }
    float eel = expf(g_EL[h * NN + i]);
    float denom = ((float)NN - deg) + eel * s;
    float v = eel * y / denom;
    out[i * 64 + t] = (v > 0.f) ? v : expm1f(v);
}

// ---------------------------------------------------------------------------
extern "C" void kernel_launch(void* const* d_in, const int* in_sizes, int n_in,
                              void* d_out, int out_size) {
    const float* A  = (const float*)d_in[0];
    const float* H  = (const float*)d_in[1];
    const float* W  = (const float*)d_in[2];
    const float* al = (const float*)d_in[3];
    const float* ar = (const float*)d_in[4];
    float* out = (float*)d_out;

    wtrans_kernel<<<8, 256>>>(W);
    prep_kernel<<<256, 256>>>(H, al, ar);
    dim3 grid(NN / GBM, KCH);
    gemm_kernel<<<grid, 256>>>(A);
    finalize_kernel<<<1024, 256>>>(out);
}